// round 14
// baseline (speedup 1.0000x reference)
#include <cuda_runtime.h>
#include <cuda_bf16.h>
#include <cstdint>
#include <math.h>

#define VOCAB  32000
#define EMBED  300
#define KA     320
#define HIDDEN 512
#define G4     2048
#define BATCH  256
#define SEQ    512
#define NOUT   7

// ---------------------------------------------------------------------------
// Device scratch
// ---------------------------------------------------------------------------
__device__ float g_gx[(size_t)SEQ * BATCH * G4];   // [s][b][gate*512+j]
__device__ __nv_bfloat16 g_hh[2][BATCH * HIDDEN];
__device__ __nv_bfloat16 g_hl[2][BATCH * HIDDEN];
__device__ __nv_bfloat16 g_Wp_hi[(size_t)HIDDEN * G4];   // [k][n'=j*4+gate]
__device__ __nv_bfloat16 g_Wp_lo[(size_t)HIDDEN * G4];
__device__ __nv_bfloat16 g_emb_hi[(size_t)VOCAB * KA];
__device__ __nv_bfloat16 g_emb_lo[(size_t)VOCAB * KA];
__device__ __nv_bfloat16 g_wih_hi[(size_t)KA * G4];
__device__ __nv_bfloat16 g_wih_lo[(size_t)KA * G4];
// per-producer epoch flags: flag[(bt*32+nt)*32] (128B padded per flag)
__device__ unsigned g_flag[4 * 32 * 32];

// ---------------------------------------------------------------------------
// Helpers
// ---------------------------------------------------------------------------
__device__ __forceinline__ float sigf(float x) {
    return 1.f / (1.f + expf(-x));
}
__device__ __forceinline__ uint32_t smem_u32(const void* p) {
    return (uint32_t)__cvta_generic_to_shared(p);
}
__device__ __forceinline__ void ldsm_x4(uint32_t* r, uint32_t a) {
    asm volatile("ldmatrix.sync.aligned.m8n8.x4.shared.b16 {%0,%1,%2,%3}, [%4];"
        : "=r"(r[0]), "=r"(r[1]), "=r"(r[2]), "=r"(r[3]) : "r"(a));
}
__device__ __forceinline__ void ldsm_x4_t(uint32_t* r, uint32_t a) {
    asm volatile("ldmatrix.sync.aligned.m8n8.x4.trans.shared.b16 {%0,%1,%2,%3}, [%4];"
        : "=r"(r[0]), "=r"(r[1]), "=r"(r[2]), "=r"(r[3]) : "r"(a));
}
__device__ __forceinline__ void mma_bf16(float* d, const uint32_t* a,
                                         uint32_t b0, uint32_t b1) {
    asm volatile(
        "mma.sync.aligned.m16n8k16.row.col.f32.bf16.bf16.f32 "
        "{%0,%1,%2,%3}, {%4,%5,%6,%7}, {%8,%9}, {%0,%1,%2,%3};"
        : "+f"(d[0]), "+f"(d[1]), "+f"(d[2]), "+f"(d[3])
        : "r"(a[0]), "r"(a[1]), "r"(a[2]), "r"(a[3]), "r"(b0), "r"(b1));
}
#define CP16(dst, src) \
    asm volatile("cp.async.cg.shared.global [%0], [%1], 16;" \
                 :: "r"(dst), "l"(src))
#define CP_COMMIT() asm volatile("cp.async.commit_group;")
#define CP_WAIT1()  asm volatile("cp.async.wait_group 1;")
#define CP_WAIT0()  asm volatile("cp.async.wait_group 0;")
#define FENCE_ACQREL_GPU() asm volatile("fence.acq_rel.gpu;" ::: "memory")

// ---------------------------------------------------------------------------
// Prep kernels
// ---------------------------------------------------------------------------
__global__ void k_prep_w(const float* __restrict__ W_hh) {
    int idx = blockIdx.x * 256 + threadIdx.x;    // = k*2048 + n'
    int k  = idx >> 11;
    int np = idx & 2047;
    int gate = np & 3, j = np >> 2;
    float w = W_hh[(size_t)(gate * HIDDEN + j) * HIDDEN + k];
    __nv_bfloat16 hi = __float2bfloat16(w);
    g_Wp_hi[idx] = hi;
    g_Wp_lo[idx] = __float2bfloat16(w - __bfloat162float(hi));
}

__global__ void k_prep_wih(const float* __restrict__ W_ih) {
    int idx = blockIdx.x * 256 + threadIdx.x;    // k*2048 + g
    int k = idx >> 11;
    int g = idx & 2047;
    float w = (k < EMBED) ? W_ih[(size_t)g * EMBED + k] : 0.f;
    __nv_bfloat16 hi = __float2bfloat16(w);
    g_wih_hi[idx] = hi;
    g_wih_lo[idx] = __float2bfloat16(w - __bfloat162float(hi));
}

__global__ void k_prep_emb(const float* __restrict__ emb) {
    size_t idx = (size_t)blockIdx.x * 256 + threadIdx.x;  // row*KA + col
    int col = (int)(idx % KA);
    int row = (int)(idx / KA);
    float v = (row != 0 && col < EMBED) ? emb[(size_t)row * EMBED + col] : 0.f;
    __nv_bfloat16 hi = __float2bfloat16(v);
    g_emb_hi[idx] = hi;
    g_emb_lo[idx] = __float2bfloat16(v - __bfloat162float(hi));
}

// ---------------------------------------------------------------------------
// Kernel A (MMA): fused embedding gather + input projection, split-bf16.
// (proven R9/R11, unchanged)
// ---------------------------------------------------------------------------
#define PITCH  72
#define AHSZ   (128 * PITCH)
#define BHSZ   (64 * PITCH)
#define BOFF   (2 * AHSZ)
#define ASTAGE (2 * AHSZ + 2 * BHSZ)
#define NCHA   5
#define SMEM_EMB (3 * ASTAGE * 2)

__global__ __launch_bounds__(512, 1) void k_embed_mma(
    const int* __restrict__ tokens, const float* __restrict__ b_ih)
{
    extern __shared__ __align__(16) __nv_bfloat16 smem[];
    __shared__ int tok_s[128];

    const int tid = threadIdx.x;
    const int n0  = blockIdx.x * 64;
    const int m0  = blockIdx.y * 128;

    if (tid < 128) {
        int r = m0 + tid;
        int s = r >> 8;
        int b = r & 255;
        tok_s[tid] = tokens[b * SEQ + s];
    }
    __syncthreads();

    const int ar   = tid >> 2;
    const int aseg = (tid & 3) * 2;
    const int br   = tid >> 3;
    const int bseg = tid & 7;

    auto issue = [&](int c) {
        __nv_bfloat16* st = smem + (c % 3) * ASTAGE;
        int k0 = c * 64;
        const size_t abase = (size_t)tok_s[ar] * KA + k0;
        #pragma unroll
        for (int t = 0; t < 2; t++) {
            int seg = aseg + t;
            uint32_t d = smem_u32(st + ar * PITCH + seg * 8);
            CP16(d,            g_emb_hi + abase + seg * 8);
            CP16(d + 2 * AHSZ, g_emb_lo + abase + seg * 8);
        }
        const size_t bbase = (size_t)(k0 + br) * G4 + n0 + bseg * 8;
        uint32_t d = smem_u32(st + BOFF + br * PITCH + bseg * 8);
        CP16(d,            g_wih_hi + bbase);
        CP16(d + 2 * BHSZ, g_wih_lo + bbase);
    };

    issue(0); CP_COMMIT();
    issue(1); CP_COMMIT();

    const int wid  = tid >> 5;
    const int lane = tid & 31;
    const int wm   = (wid & 7) * 16;
    const int wn   = (wid >> 3) * 32;

    const int a_row = wm + (lane & 15);
    const int a_co  = (lane >> 4) * 8;
    const int b_ro  = (lane & 15);

    float accm[4][4], acc1[4][4], acc2[4][4];
    #pragma unroll
    for (int nt = 0; nt < 4; nt++)
        #pragma unroll
        for (int i = 0; i < 4; i++) {
            accm[nt][i] = 0.f; acc1[nt][i] = 0.f; acc2[nt][i] = 0.f;
        }

    for (int c = 0; c < NCHA; c++) {
        CP_WAIT1();
        __syncthreads();
        if (c + 2 < NCHA) issue(c + 2);
        CP_COMMIT();

        const __nv_bfloat16* st = smem + (c % 3) * ASTAGE;
        const __nv_bfloat16* Ah = st;
        const __nv_bfloat16* Al = st + AHSZ;
        const __nv_bfloat16* Bh = st + BOFF;
        const __nv_bfloat16* Bl = st + BOFF + BHSZ;

        #pragma unroll
        for (int ks = 0; ks < 4; ks++) {
            uint32_t ahi[4], alo[4], bhi[8], blo[8];
            ldsm_x4(ahi, smem_u32(Ah + a_row * PITCH + ks * 16 + a_co));
            ldsm_x4(alo, smem_u32(Al + a_row * PITCH + ks * 16 + a_co));
            int kr = ks * 16 + b_ro;
            int bc0 = wn + (lane >> 4) * 8;
            ldsm_x4_t(bhi,     smem_u32(Bh + kr * PITCH + bc0));
            ldsm_x4_t(bhi + 4, smem_u32(Bh + kr * PITCH + bc0 + 16));
            ldsm_x4_t(blo,     smem_u32(Bl + kr * PITCH + bc0));
            ldsm_x4_t(blo + 4, smem_u32(Bl + kr * PITCH + bc0 + 16));
            #pragma unroll
            for (int nt = 0; nt < 4; nt++) {
                mma_bf16(accm[nt], ahi, bhi[nt * 2], bhi[nt * 2 + 1]);
                mma_bf16(acc1[nt], ahi, blo[nt * 2], blo[nt * 2 + 1]);
                mma_bf16(acc2[nt], alo, bhi[nt * 2], bhi[nt * 2 + 1]);
            }
        }
    }

    #pragma unroll
    for (int nt = 0; nt < 4; nt++) {
        int col = n0 + wn + nt * 8 + (lane & 3) * 2;
        float2 bias = *(const float2*)&b_ih[col];
        float c0 = accm[nt][0] + acc1[nt][0] + acc2[nt][0] + bias.x;
        float c1 = accm[nt][1] + acc1[nt][1] + acc2[nt][1] + bias.y;
        float c2 = accm[nt][2] + acc1[nt][2] + acc2[nt][2] + bias.x;
        float c3 = accm[nt][3] + acc1[nt][3] + acc2[nt][3] + bias.y;
        size_t r0 = (size_t)(m0 + wm + (lane >> 2));
        __stcg((float2*)&g_gx[r0 * G4 + col],       make_float2(c0, c1));
        __stcg((float2*)&g_gx[(r0 + 8) * G4 + col], make_float2(c2, c3));
    }
}

// ---------------------------------------------------------------------------
// Persistent LSTM kernel (split-bf16 mma.sync, W resident in SMEM).
// v5: R11 structure, but the 32-CTA epoch barrier is replaced by
// fine-grained per-producer flags.  Chunk c of step s needs h j-rows from
// producers nt = 4c..4c+3 only; warp 0 polls those 4 flags just-in-time
// (2 chunks ahead), so a CTA starts its step as soon as producers 0..7
// finished the previous step — straggler skew overlaps the GEMM.
// ---------------------------------------------------------------------------
#define WSPLIT  (HIDDEN * PITCH)
#define RING0   (2 * WSPLIT)
#define HTILE   (64 * PITCH)
#define HSTAGE  (2 * HTILE)
#define GXS_OFF (RING0 + 3 * HSTAGE)
#define SMEM_PERSIST ((GXS_OFF + 8192) * 2)

__global__ __launch_bounds__(512, 1) void k_lstm_persist(
    const float* __restrict__ b_hh)
{
    extern __shared__ __align__(16) __nv_bfloat16 smem[];
    float* Csm = (float*)(smem + RING0);
    float* gxs = (float*)(smem + GXS_OFF);

    const int tid = threadIdx.x;
    const int cta = blockIdx.x;
    const int nt  = cta & 31;
    const int n0  = nt * 64;
    const int bt  = cta >> 5;            // b-group 0..3
    const int b0  = bt * 64;
    const int jt0 = n0 >> 2;

    volatile unsigned* flg = g_flag + (size_t)bt * 32 * 32;   // [nt]*32
    volatile unsigned* myflag = flg + nt * 32;

    #pragma unroll
    for (int x = 0; x < 8; x++) {
        int o   = tid + x * 512;
        int k   = o >> 3;
        int seg = (o & 7) * 8;
        uint32_t d = smem_u32(smem + k * PITCH + seg);
        CP16(d, g_Wp_hi + (size_t)k * G4 + n0 + seg);
        uint32_t d2 = smem_u32(smem + WSPLIT + k * PITCH + seg);
        CP16(d2, g_Wp_lo + (size_t)k * G4 + n0 + seg);
    }
    CP_COMMIT();

    float bh[2][4], creg[2];
    #pragma unroll
    for (int t = 0; t < 2; t++) {
        int idx = tid + t * 512;
        int jl  = idx & 15;
        int j   = jt0 + jl;
        creg[t] = 0.f;
        #pragma unroll
        for (int g = 0; g < 4; g++) bh[t][g] = b_hh[g * HIDDEN + j];
    }

    CP_WAIT0();
    __syncthreads();

    const int ld_row = tid >> 3;
    const int ld_c0  = (tid & 7) * 8;

    const int wid  = tid >> 5;
    const int lane = tid & 31;
    const int wb   = (wid & 3) * 16;
    const int wn   = (wid >> 2) * 16;
    const int a_row = wb + (lane & 15);
    const int a_co  = (lane >> 4) * 8;
    const int b_ro  = (lane & 15);
    const int b_co  = wn + (lane >> 4) * 8;

    for (int s = 0; s < SEQ; s++) {
        const __nv_bfloat16* __restrict__ hhi = g_hh[s & 1];
        const __nv_bfloat16* __restrict__ hlo = g_hl[s & 1];
        __nv_bfloat16* __restrict__ ohh = g_hh[(s & 1) ^ 1];
        __nv_bfloat16* __restrict__ ohl = g_hl[(s & 1) ^ 1];

        // ---- wait for producers of chunks 0,1 (flags >= s) ----
        if (wid == 0 && lane < 8) {
            while (flg[lane * 32] < (unsigned)s) { }
            FENCE_ACQREL_GPU();
        }
        __syncthreads();

        // ---- gx prefetch + h chunks 0,1 ----
        {
            const float* gbase = g_gx + ((size_t)s * BATCH + b0) * G4 + jt0;
            #pragma unroll
            for (int t = 0; t < 2; t++) {
                int o = tid * 2 + t;
                int b = o >> 4, gate = (o >> 2) & 3, q = (o & 3) * 4;
                uint32_t d = smem_u32(gxs + b * 64 + gate * 16 + q);
                CP16(d, gbase + (size_t)b * G4 + gate * HIDDEN + q);
            }
        }
        #pragma unroll
        for (int c0 = 0; c0 < 2; c0++) {
            __nv_bfloat16* st = smem + RING0 + c0 * HSTAGE;
            uint32_t d = smem_u32(st + ld_row * PITCH + ld_c0);
            const size_t off = (size_t)(b0 + ld_row) * HIDDEN + c0 * 64 + ld_c0;
            CP16(d,                hhi + off);
            CP16(d + 2 * HTILE,    hlo + off);
            CP_COMMIT();
        }

        float accm[2][4], acc1[2][4], acc2[2][4];
        #pragma unroll
        for (int nq = 0; nq < 2; nq++)
            #pragma unroll
            for (int i = 0; i < 4; i++) {
                accm[nq][i] = 0.f; acc1[nq][i] = 0.f; acc2[nq][i] = 0.f;
            }

        for (int c = 0; c < 8; c++) {
            // poll flags for chunk c+2 producers before the chunk barrier
            if (c + 2 < 8 && wid == 0 && lane < 4) {
                while (flg[((c + 2) * 4 + lane) * 32] < (unsigned)s) { }
                FENCE_ACQREL_GPU();
            }
            CP_WAIT1();
            __syncthreads();
            if (c + 2 < 8) {
                int cn = c + 2;
                __nv_bfloat16* st = smem + RING0 + (cn % 3) * HSTAGE;
                uint32_t d = smem_u32(st + ld_row * PITCH + ld_c0);
                const size_t off =
                    (size_t)(b0 + ld_row) * HIDDEN + cn * 64 + ld_c0;
                CP16(d,             hhi + off);
                CP16(d + 2 * HTILE, hlo + off);
            }
            CP_COMMIT();

            const __nv_bfloat16* Ah = smem + RING0 + (c % 3) * HSTAGE;
            const __nv_bfloat16* Al = Ah + HTILE;

            #pragma unroll
            for (int ks = 0; ks < 4; ks++) {
                uint32_t ahi[4], alo[4], bhi[4], blo[4];
                ldsm_x4(ahi, smem_u32(Ah + a_row * PITCH + ks * 16 + a_co));
                ldsm_x4(alo, smem_u32(Al + a_row * PITCH + ks * 16 + a_co));
                int krow = c * 64 + ks * 16 + b_ro;
                ldsm_x4_t(bhi, smem_u32(smem + krow * PITCH + b_co));
                ldsm_x4_t(blo, smem_u32(smem + WSPLIT + krow * PITCH + b_co));
                #pragma unroll
                for (int nq = 0; nq < 2; nq++) {
                    mma_bf16(accm[nq], ahi, bhi[nq * 2], bhi[nq * 2 + 1]);
                    mma_bf16(acc1[nq], ahi, blo[nq * 2], blo[nq * 2 + 1]);
                    mma_bf16(acc2[nq], alo, bhi[nq * 2], bhi[nq * 2 + 1]);
                }
            }
        }

        #pragma unroll
        for (int nq = 0; nq < 2; nq++)
            #pragma unroll
            for (int i = 0; i < 4; i++)
                accm[nq][i] += acc1[nq][i] + acc2[nq][i];

        // stage C into SMEM (stage-0 alias; last read during c=6, all
        // warps passed the c=7 barrier; disjoint 16x16 tiles per warp)
        #pragma unroll
        for (int nq = 0; nq < 2; nq++) {
            int r0  = wb + (lane >> 2);
            int col = wn + nq * 8 + (lane & 3) * 2;
            *(float2*)&Csm[r0 * 68 + col] =
                make_float2(accm[nq][0], accm[nq][1]);
            *(float2*)&Csm[(r0 + 8) * 68 + col] =
                make_float2(accm[nq][2], accm[nq][3]);
        }
        __syncthreads();

        #pragma unroll
        for (int t = 0; t < 2; t++) {
            int idx = tid + t * 512;
            int jl = idx & 15, bl = idx >> 4;
            int b = b0 + bl, j = jt0 + jl;
            float4 gq = *(const float4*)&Csm[bl * 68 + jl * 4];  // i,f,g,o
            const float* gr = gxs + bl * 64;
            float gi = gq.x + gr[jl]      + bh[t][0];
            float gf = gq.y + gr[16 + jl] + bh[t][1];
            float gg = gq.z + gr[32 + jl] + bh[t][2];
            float go = gq.w + gr[48 + jl] + bh[t][3];
            float ig = sigf(gi), fg = sigf(gf);
            float gv = tanhf(gg), og = sigf(go);
            float cn = fg * creg[t] + ig * gv;
            creg[t] = cn;
            float hn = og * tanhf(cn);
            int ci = b * HIDDEN + j;
            __nv_bfloat16 hi = __float2bfloat16(hn);
            ohh[ci] = hi;
            ohl[ci] = __float2bfloat16(hn - __bfloat162float(hi));
        }

        // ---- publish: my h rows for step s+1 are ready ----
        __syncthreads();
        if (tid == 0) {
            FENCE_ACQREL_GPU();          // release h stores
            myflag[0] = (unsigned)(s + 1);
        }
        // no further CTA barrier: next-step polls order everything
    }
}

// ---------------------------------------------------------------------------
// Init
// ---------------------------------------------------------------------------
__global__ void k_init() {
    int i = blockIdx.x * blockDim.x + threadIdx.x;
    if (i < BATCH * HIDDEN) {
        g_hh[0][i] = __float2bfloat16(0.f);
        g_hl[0][i] = __float2bfloat16(0.f);
    }
    if (i < 4 * 32 * 32) g_flag[i] = 0u;
}

// ---------------------------------------------------------------------------
// Kernel C: logits = h_T @ W_fc^T + b_fc
// ---------------------------------------------------------------------------
__global__ __launch_bounds__(128) void k_fc(
    const float* __restrict__ W_fc, const float* __restrict__ b_fc,
    float* __restrict__ out)
{
    const int b   = blockIdx.x;
    const int tid = threadIdx.x;

    float p[NOUT];
    #pragma unroll
    for (int o = 0; o < NOUT; o++) p[o] = 0.f;

    for (int jj = tid; jj < HIDDEN; jj += 128) {
        float hv = __bfloat162float(g_hh[0][b * HIDDEN + jj]) +
                   __bfloat162float(g_hl[0][b * HIDDEN + jj]);
        #pragma unroll
        for (int o = 0; o < NOUT; o++) p[o] += hv * W_fc[o * HIDDEN + jj];
    }

    __shared__ float redm[NOUT][128];
    #pragma unroll
    for (int o = 0; o < NOUT; o++) redm[o][tid] = p[o];
    __syncthreads();
    for (int st = 64; st > 0; st >>= 1) {
        if (tid < st) {
            #pragma unroll
            for (int o = 0; o < NOUT; o++) redm[o][tid] += redm[o][tid + st];
        }
        __syncthreads();
    }
    if (tid < NOUT) out[b * NOUT + tid] = redm[tid][0] + b_fc[tid];
}

// ---------------------------------------------------------------------------
// Launch
// ---------------------------------------------------------------------------
extern "C" void kernel_launch(void* const* d_in, const int* in_sizes, int n_in,
                              void* d_out, int out_size)
{
    const int*   tokens = (const int*)  d_in[0];
    const float* emb    = (const float*)d_in[1];
    const float* W_ih   = (const float*)d_in[2];
    const float* b_ih   = (const float*)d_in[3];
    const float* W_hh   = (const float*)d_in[4];
    const float* b_hh   = (const float*)d_in[5];
    const float* W_fc   = (const float*)d_in[6];
    const float* b_fc   = (const float*)d_in[7];
    float* out = (float*)d_out;

    static bool attr_set = false;
    if (!attr_set) {
        cudaFuncSetAttribute(k_lstm_persist,
                             cudaFuncAttributeMaxDynamicSharedMemorySize,
                             SMEM_PERSIST);
        cudaFuncSetAttribute(k_embed_mma,
                             cudaFuncAttributeMaxDynamicSharedMemorySize,
                             SMEM_EMB);
        attr_set = true;
    }

    k_init<<<(BATCH * HIDDEN + 255) / 256, 256>>>();
    k_prep_w<<<(HIDDEN * G4) / 256, 256>>>(W_hh);
    k_prep_wih<<<(KA * G4) / 256, 256>>>(W_ih);
    k_prep_emb<<<((size_t)VOCAB * KA) / 256, 256>>>(emb);

    dim3 gE(G4 / 64, (BATCH * SEQ) / 128);   // (32, 1024)
    k_embed_mma<<<gE, 512, SMEM_EMB>>>(tokens, b_ih);

    k_lstm_persist<<<128, 512, SMEM_PERSIST>>>(b_hh);

    k_fc<<<BATCH, 128>>>(W_fc, b_fc, out);
}

// round 15
// speedup vs baseline: 1.3885x; 1.3885x over previous
#include <cuda_runtime.h>
#include <cuda_bf16.h>
#include <cstdint>
#include <math.h>

#define VOCAB  32000
#define EMBED  300
#define KA     320
#define HIDDEN 512
#define G4     2048
#define BATCH  256
#define SEQ    512
#define NOUT   7

// ---------------------------------------------------------------------------
// Device scratch
// ---------------------------------------------------------------------------
__device__ float g_gx[(size_t)SEQ * BATCH * G4];   // [s][b][gate*512+j]
__device__ __nv_bfloat16 g_hh[2][BATCH * HIDDEN];
__device__ __nv_bfloat16 g_hl[2][BATCH * HIDDEN];
__device__ __nv_bfloat16 g_Wp_hi[(size_t)HIDDEN * G4];   // [k][n'=j*4+gate]
__device__ __nv_bfloat16 g_Wp_lo[(size_t)HIDDEN * G4];
__device__ __nv_bfloat16 g_emb_hi[(size_t)VOCAB * KA];
__device__ __nv_bfloat16 g_emb_lo[(size_t)VOCAB * KA];
__device__ __nv_bfloat16 g_wih_hi[(size_t)KA * G4];
__device__ __nv_bfloat16 g_wih_lo[(size_t)KA * G4];
// 4 independent sub-group barriers (one per 64-batch tile), 128B padded
__device__ unsigned g_cnt4[4 * 32];
__device__ unsigned g_epoch4[4 * 32];

// ---------------------------------------------------------------------------
// Helpers
// ---------------------------------------------------------------------------
__device__ __forceinline__ float sigf(float x) {
    return 1.f / (1.f + expf(-x));
}
__device__ __forceinline__ uint32_t smem_u32(const void* p) {
    return (uint32_t)__cvta_generic_to_shared(p);
}
__device__ __forceinline__ void ldsm_x4(uint32_t* r, uint32_t a) {
    asm volatile("ldmatrix.sync.aligned.m8n8.x4.shared.b16 {%0,%1,%2,%3}, [%4];"
        : "=r"(r[0]), "=r"(r[1]), "=r"(r[2]), "=r"(r[3]) : "r"(a));
}
__device__ __forceinline__ void ldsm_x4_t(uint32_t* r, uint32_t a) {
    asm volatile("ldmatrix.sync.aligned.m8n8.x4.trans.shared.b16 {%0,%1,%2,%3}, [%4];"
        : "=r"(r[0]), "=r"(r[1]), "=r"(r[2]), "=r"(r[3]) : "r"(a));
}
__device__ __forceinline__ void mma_bf16(float* d, const uint32_t* a,
                                         uint32_t b0, uint32_t b1) {
    asm volatile(
        "mma.sync.aligned.m16n8k16.row.col.f32.bf16.bf16.f32 "
        "{%0,%1,%2,%3}, {%4,%5,%6,%7}, {%8,%9}, {%0,%1,%2,%3};"
        : "+f"(d[0]), "+f"(d[1]), "+f"(d[2]), "+f"(d[3])
        : "r"(a[0]), "r"(a[1]), "r"(a[2]), "r"(a[3]), "r"(b0), "r"(b1));
}
#define CP16(dst, src) \
    asm volatile("cp.async.cg.shared.global [%0], [%1], 16;" \
                 :: "r"(dst), "l"(src))
#define CP_COMMIT() asm volatile("cp.async.commit_group;")
#define CP_WAIT1()  asm volatile("cp.async.wait_group 1;")
#define CP_WAIT2()  asm volatile("cp.async.wait_group 2;")
#define CP_WAIT0()  asm volatile("cp.async.wait_group 0;")
#define FENCE_ACQREL_GPU() asm volatile("fence.acq_rel.gpu;" ::: "memory")

// ---------------------------------------------------------------------------
// Prep kernels
// ---------------------------------------------------------------------------
__global__ void k_prep_w(const float* __restrict__ W_hh) {
    int idx = blockIdx.x * 256 + threadIdx.x;    // = k*2048 + n'
    int k  = idx >> 11;
    int np = idx & 2047;
    int gate = np & 3, j = np >> 2;
    float w = W_hh[(size_t)(gate * HIDDEN + j) * HIDDEN + k];
    __nv_bfloat16 hi = __float2bfloat16(w);
    g_Wp_hi[idx] = hi;
    g_Wp_lo[idx] = __float2bfloat16(w - __bfloat162float(hi));
}

__global__ void k_prep_wih(const float* __restrict__ W_ih) {
    int idx = blockIdx.x * 256 + threadIdx.x;    // k*2048 + g
    int k = idx >> 11;
    int g = idx & 2047;
    float w = (k < EMBED) ? W_ih[(size_t)g * EMBED + k] : 0.f;
    __nv_bfloat16 hi = __float2bfloat16(w);
    g_wih_hi[idx] = hi;
    g_wih_lo[idx] = __float2bfloat16(w - __bfloat162float(hi));
}

__global__ void k_prep_emb(const float* __restrict__ emb) {
    size_t idx = (size_t)blockIdx.x * 256 + threadIdx.x;  // row*KA + col
    int col = (int)(idx % KA);
    int row = (int)(idx / KA);
    float v = (row != 0 && col < EMBED) ? emb[(size_t)row * EMBED + col] : 0.f;
    __nv_bfloat16 hi = __float2bfloat16(v);
    g_emb_hi[idx] = hi;
    g_emb_lo[idx] = __float2bfloat16(v - __bfloat162float(hi));
}

// ---------------------------------------------------------------------------
// Kernel A (MMA): fused embedding gather + input projection, split-bf16.
// (proven R9/R11, unchanged)
// ---------------------------------------------------------------------------
#define PITCH  72
#define AHSZ   (128 * PITCH)
#define BHSZ   (64 * PITCH)
#define BOFF   (2 * AHSZ)
#define ASTAGE (2 * AHSZ + 2 * BHSZ)
#define NCHA   5
#define SMEM_EMB (3 * ASTAGE * 2)

__global__ __launch_bounds__(512, 1) void k_embed_mma(
    const int* __restrict__ tokens, const float* __restrict__ b_ih)
{
    extern __shared__ __align__(16) __nv_bfloat16 smem[];
    __shared__ int tok_s[128];

    const int tid = threadIdx.x;
    const int n0  = blockIdx.x * 64;
    const int m0  = blockIdx.y * 128;

    if (tid < 128) {
        int r = m0 + tid;
        int s = r >> 8;
        int b = r & 255;
        tok_s[tid] = tokens[b * SEQ + s];
    }
    __syncthreads();

    const int ar   = tid >> 2;
    const int aseg = (tid & 3) * 2;
    const int br   = tid >> 3;
    const int bseg = tid & 7;

    auto issue = [&](int c) {
        __nv_bfloat16* st = smem + (c % 3) * ASTAGE;
        int k0 = c * 64;
        const size_t abase = (size_t)tok_s[ar] * KA + k0;
        #pragma unroll
        for (int t = 0; t < 2; t++) {
            int seg = aseg + t;
            uint32_t d = smem_u32(st + ar * PITCH + seg * 8);
            CP16(d,            g_emb_hi + abase + seg * 8);
            CP16(d + 2 * AHSZ, g_emb_lo + abase + seg * 8);
        }
        const size_t bbase = (size_t)(k0 + br) * G4 + n0 + bseg * 8;
        uint32_t d = smem_u32(st + BOFF + br * PITCH + bseg * 8);
        CP16(d,            g_wih_hi + bbase);
        CP16(d + 2 * BHSZ, g_wih_lo + bbase);
    };

    issue(0); CP_COMMIT();
    issue(1); CP_COMMIT();

    const int wid  = tid >> 5;
    const int lane = tid & 31;
    const int wm   = (wid & 7) * 16;
    const int wn   = (wid >> 3) * 32;

    const int a_row = wm + (lane & 15);
    const int a_co  = (lane >> 4) * 8;
    const int b_ro  = (lane & 15);

    float accm[4][4], acc1[4][4], acc2[4][4];
    #pragma unroll
    for (int nt = 0; nt < 4; nt++)
        #pragma unroll
        for (int i = 0; i < 4; i++) {
            accm[nt][i] = 0.f; acc1[nt][i] = 0.f; acc2[nt][i] = 0.f;
        }

    for (int c = 0; c < NCHA; c++) {
        CP_WAIT1();
        __syncthreads();
        if (c + 2 < NCHA) issue(c + 2);
        CP_COMMIT();

        const __nv_bfloat16* st = smem + (c % 3) * ASTAGE;
        const __nv_bfloat16* Ah = st;
        const __nv_bfloat16* Al = st + AHSZ;
        const __nv_bfloat16* Bh = st + BOFF;
        const __nv_bfloat16* Bl = st + BOFF + BHSZ;

        #pragma unroll
        for (int ks = 0; ks < 4; ks++) {
            uint32_t ahi[4], alo[4], bhi[8], blo[8];
            ldsm_x4(ahi, smem_u32(Ah + a_row * PITCH + ks * 16 + a_co));
            ldsm_x4(alo, smem_u32(Al + a_row * PITCH + ks * 16 + a_co));
            int kr = ks * 16 + b_ro;
            int bc0 = wn + (lane >> 4) * 8;
            ldsm_x4_t(bhi,     smem_u32(Bh + kr * PITCH + bc0));
            ldsm_x4_t(bhi + 4, smem_u32(Bh + kr * PITCH + bc0 + 16));
            ldsm_x4_t(blo,     smem_u32(Bl + kr * PITCH + bc0));
            ldsm_x4_t(blo + 4, smem_u32(Bl + kr * PITCH + bc0 + 16));
            #pragma unroll
            for (int nt = 0; nt < 4; nt++) {
                mma_bf16(accm[nt], ahi, bhi[nt * 2], bhi[nt * 2 + 1]);
                mma_bf16(acc1[nt], ahi, blo[nt * 2], blo[nt * 2 + 1]);
                mma_bf16(acc2[nt], alo, bhi[nt * 2], bhi[nt * 2 + 1]);
            }
        }
    }

    #pragma unroll
    for (int nt = 0; nt < 4; nt++) {
        int col = n0 + wn + nt * 8 + (lane & 3) * 2;
        float2 bias = *(const float2*)&b_ih[col];
        float c0 = accm[nt][0] + acc1[nt][0] + acc2[nt][0] + bias.x;
        float c1 = accm[nt][1] + acc1[nt][1] + acc2[nt][1] + bias.y;
        float c2 = accm[nt][2] + acc1[nt][2] + acc2[nt][2] + bias.x;
        float c3 = accm[nt][3] + acc1[nt][3] + acc2[nt][3] + bias.y;
        size_t r0 = (size_t)(m0 + wm + (lane >> 2));
        __stcg((float2*)&g_gx[r0 * G4 + col],       make_float2(c0, c1));
        __stcg((float2*)&g_gx[(r0 + 8) * G4 + col], make_float2(c2, c3));
    }
}

// ---------------------------------------------------------------------------
// Persistent LSTM kernel (split-bf16 mma.sync, W resident in SMEM).
// v6 = R11 + two latency fixes:
//   (1) 4-stage h ring (issue 3 chunks ahead, wait_group 2) — covers the
//       h L2 latency with ~3000 cyc of slack instead of ~400.
//   (2) gx epilogue operands loaded to REGISTERS at step top (__ldg,
//       consumed ~8 us later) — frees 16 KB smem for the 4th stage and
//       removes the gxs smem round-trip.
// Everything else (MMA core, 32-CTA epoch barrier, aliasing) is R11-proven.
// ---------------------------------------------------------------------------
#define WSPLIT  (HIDDEN * PITCH)           // 36864 elems per W split
#define RING0   (2 * WSPLIT)               // 73728 elems
#define HTILE   (64 * PITCH)               // 4608 elems per split per stage
#define HSTAGE  (2 * HTILE)                // 9216 elems per ring stage
#define NSTG    4
#define SMEM_PERSIST ((RING0 + NSTG * HSTAGE) * 2)   // 221,184 B

__global__ __launch_bounds__(512, 1) void k_lstm_persist(
    const float* __restrict__ b_hh)
{
    extern __shared__ __align__(16) __nv_bfloat16 smem[];
    float* Csm = (float*)(smem + RING0);   // aliases ring stage 0 (17.4 KB)

    const int tid = threadIdx.x;
    const int cta = blockIdx.x;
    const int n0  = (cta & 31) * 64;
    const int bt  = cta >> 5;            // b-group 0..3
    const int b0  = bt * 64;
    const int jt0 = n0 >> 2;

    unsigned* cntp   = &g_cnt4[bt * 32];
    unsigned* epochp = &g_epoch4[bt * 32];

    // ---- one-time W load ----
    #pragma unroll
    for (int x = 0; x < 8; x++) {
        int o   = tid + x * 512;
        int k   = o >> 3;
        int seg = (o & 7) * 8;
        uint32_t d = smem_u32(smem + k * PITCH + seg);
        CP16(d, g_Wp_hi + (size_t)k * G4 + n0 + seg);
        uint32_t d2 = smem_u32(smem + WSPLIT + k * PITCH + seg);
        CP16(d2, g_Wp_lo + (size_t)k * G4 + n0 + seg);
    }
    CP_COMMIT();

    float bh[2][4], creg[2];
    #pragma unroll
    for (int t = 0; t < 2; t++) {
        int idx = tid + t * 512;
        int jl  = idx & 15;
        int j   = jt0 + jl;
        creg[t] = 0.f;
        #pragma unroll
        for (int g = 0; g < 4; g++) bh[t][g] = b_hh[g * HIDDEN + j];
    }

    CP_WAIT0();
    __syncthreads();

    const int ld_row = tid >> 3;
    const int ld_c0  = (tid & 7) * 8;

    const int wid  = tid >> 5;
    const int lane = tid & 31;
    const int wb   = (wid & 3) * 16;
    const int wn   = (wid >> 2) * 16;
    const int a_row = wb + (lane & 15);
    const int a_co  = (lane >> 4) * 8;
    const int b_ro  = (lane & 15);
    const int b_co  = wn + (lane >> 4) * 8;

    for (int s = 0; s < SEQ; s++) {
        const __nv_bfloat16* __restrict__ hhi = g_hh[s & 1];
        const __nv_bfloat16* __restrict__ hlo = g_hl[s & 1];
        __nv_bfloat16* __restrict__ ohh = g_hh[(s & 1) ^ 1];
        __nv_bfloat16* __restrict__ ohl = g_hl[(s & 1) ^ 1];

        // ---- gx prefetch into REGISTERS (hidden behind the whole GEMM) ----
        float gq[2][4];
        #pragma unroll
        for (int t = 0; t < 2; t++) {
            int idx = tid + t * 512;
            int jl = idx & 15, bl = idx >> 4;
            const float* gp = g_gx +
                ((size_t)s * BATCH + b0 + bl) * G4 + jt0 + jl;
            #pragma unroll
            for (int g = 0; g < 4; g++) gq[t][g] = __ldg(gp + g * HIDDEN);
        }

        auto issueA = [&](int c) {
            __nv_bfloat16* st = smem + RING0 + (c % NSTG) * HSTAGE;
            uint32_t d = smem_u32(st + ld_row * PITCH + ld_c0);
            const size_t off = (size_t)(b0 + ld_row) * HIDDEN + c * 64 + ld_c0;
            CP16(d,             hhi + off);
            CP16(d + 2 * HTILE, hlo + off);   // byte offset = HTILE elems
        };

        // prologue: 3 chunks in flight
        issueA(0); CP_COMMIT();
        issueA(1); CP_COMMIT();
        issueA(2); CP_COMMIT();

        float accm[2][4], acc1[2][4], acc2[2][4];
        #pragma unroll
        for (int nq = 0; nq < 2; nq++)
            #pragma unroll
            for (int i = 0; i < 4; i++) {
                accm[nq][i] = 0.f; acc1[nq][i] = 0.f; acc2[nq][i] = 0.f;
            }

        for (int c = 0; c < 8; c++) {
            CP_WAIT2();          // chunk c arrived (groups complete in order)
            __syncthreads();     // ring buffer (c+3)%4 free: chunk c-1 reads done
            if (c + 3 < 8) issueA(c + 3);
            CP_COMMIT();

            const __nv_bfloat16* Ah = smem + RING0 + (c % NSTG) * HSTAGE;
            const __nv_bfloat16* Al = Ah + HTILE;

            #pragma unroll
            for (int ks = 0; ks < 4; ks++) {
                uint32_t ahi[4], alo[4], bhi[4], blo[4];
                ldsm_x4(ahi, smem_u32(Ah + a_row * PITCH + ks * 16 + a_co));
                ldsm_x4(alo, smem_u32(Al + a_row * PITCH + ks * 16 + a_co));
                int krow = c * 64 + ks * 16 + b_ro;
                ldsm_x4_t(bhi, smem_u32(smem + krow * PITCH + b_co));
                ldsm_x4_t(blo, smem_u32(smem + WSPLIT + krow * PITCH + b_co));
                #pragma unroll
                for (int nq = 0; nq < 2; nq++) {
                    mma_bf16(accm[nq], ahi, bhi[nq * 2], bhi[nq * 2 + 1]);
                    mma_bf16(acc1[nq], ahi, blo[nq * 2], blo[nq * 2 + 1]);
                    mma_bf16(acc2[nq], alo, bhi[nq * 2], bhi[nq * 2 + 1]);
                }
            }
        }

        #pragma unroll
        for (int nq = 0; nq < 2; nq++)
            #pragma unroll
            for (int i = 0; i < 4; i++)
                accm[nq][i] += acc1[nq][i] + acc2[nq][i];

        // stage C into SMEM (aliases ring stage 0: last read during chunk 4,
        // all warps passed the c=5..7 barriers since; last cp.async write to
        // stage 0 was chunk 4's, completed before chunk-4 wait).  Each warp
        // writes its own disjoint 16x16 tile.
        __syncthreads();
        #pragma unroll
        for (int nq = 0; nq < 2; nq++) {
            int r0  = wb + (lane >> 2);
            int col = wn + nq * 8 + (lane & 3) * 2;
            *(float2*)&Csm[r0 * 68 + col] =
                make_float2(accm[nq][0], accm[nq][1]);
            *(float2*)&Csm[(r0 + 8) * 68 + col] =
                make_float2(accm[nq][2], accm[nq][3]);
        }
        __syncthreads();

        #pragma unroll
        for (int t = 0; t < 2; t++) {
            int idx = tid + t * 512;
            int jl = idx & 15, bl = idx >> 4;
            int b = b0 + bl, j = jt0 + jl;
            float4 cq = *(const float4*)&Csm[bl * 68 + jl * 4];  // i,f,g,o
            float gi = cq.x + gq[t][0] + bh[t][0];
            float gf = cq.y + gq[t][1] + bh[t][1];
            float gg = cq.z + gq[t][2] + bh[t][2];
            float go = cq.w + gq[t][3] + bh[t][3];
            float ig = sigf(gi), fg = sigf(gf);
            float gv = tanhf(gg), og = sigf(go);
            float cn = fg * creg[t] + ig * gv;
            creg[t] = cn;
            float hn = og * tanhf(cn);
            int ci = b * HIDDEN + j;
            __nv_bfloat16 hi = __float2bfloat16(hn);
            ohh[ci] = hi;
            ohl[ci] = __float2bfloat16(hn - __bfloat162float(hi));
        }

        // ---- sub-group epoch barrier (32 CTAs sharing this b-group) ----
        __syncthreads();
        if (tid == 0) {
            FENCE_ACQREL_GPU();
            unsigned a = atomicAdd(cntp, 1u);
            if (a == 31u) {
                *cntp = 0u;
                FENCE_ACQREL_GPU();
                *(volatile unsigned*)epochp = (unsigned)(s + 1);
            } else {
                while (*(volatile unsigned*)epochp < (unsigned)(s + 1)) { }
                FENCE_ACQREL_GPU();
            }
        }
        __syncthreads();
    }
}

// ---------------------------------------------------------------------------
// Init
// ---------------------------------------------------------------------------
__global__ void k_init() {
    int i = blockIdx.x * blockDim.x + threadIdx.x;
    if (i < BATCH * HIDDEN) {
        g_hh[0][i] = __float2bfloat16(0.f);
        g_hl[0][i] = __float2bfloat16(0.f);
    }
    if (i < 4 * 32) { g_cnt4[i] = 0u; g_epoch4[i] = 0u; }
}

// ---------------------------------------------------------------------------
// Kernel C: logits = h_T @ W_fc^T + b_fc
// ---------------------------------------------------------------------------
__global__ __launch_bounds__(128) void k_fc(
    const float* __restrict__ W_fc, const float* __restrict__ b_fc,
    float* __restrict__ out)
{
    const int b   = blockIdx.x;
    const int tid = threadIdx.x;

    float p[NOUT];
    #pragma unroll
    for (int o = 0; o < NOUT; o++) p[o] = 0.f;

    for (int jj = tid; jj < HIDDEN; jj += 128) {
        float hv = __bfloat162float(g_hh[0][b * HIDDEN + jj]) +
                   __bfloat162float(g_hl[0][b * HIDDEN + jj]);
        #pragma unroll
        for (int o = 0; o < NOUT; o++) p[o] += hv * W_fc[o * HIDDEN + jj];
    }

    __shared__ float redm[NOUT][128];
    #pragma unroll
    for (int o = 0; o < NOUT; o++) redm[o][tid] = p[o];
    __syncthreads();
    for (int st = 64; st > 0; st >>= 1) {
        if (tid < st) {
            #pragma unroll
            for (int o = 0; o < NOUT; o++) redm[o][tid] += redm[o][tid + st];
        }
        __syncthreads();
    }
    if (tid < NOUT) out[b * NOUT + tid] = redm[tid][0] + b_fc[tid];
}

// ---------------------------------------------------------------------------
// Launch
// ---------------------------------------------------------------------------
extern "C" void kernel_launch(void* const* d_in, const int* in_sizes, int n_in,
                              void* d_out, int out_size)
{
    const int*   tokens = (const int*)  d_in[0];
    const float* emb    = (const float*)d_in[1];
    const float* W_ih   = (const float*)d_in[2];
    const float* b_ih   = (const float*)d_in[3];
    const float* W_hh   = (const float*)d_in[4];
    const float* b_hh   = (const float*)d_in[5];
    const float* W_fc   = (const float*)d_in[6];
    const float* b_fc   = (const float*)d_in[7];
    float* out = (float*)d_out;

    static bool attr_set = false;
    if (!attr_set) {
        cudaFuncSetAttribute(k_lstm_persist,
                             cudaFuncAttributeMaxDynamicSharedMemorySize,
                             SMEM_PERSIST);
        cudaFuncSetAttribute(k_embed_mma,
                             cudaFuncAttributeMaxDynamicSharedMemorySize,
                             SMEM_EMB);
        attr_set = true;
    }

    k_init<<<(BATCH * HIDDEN + 255) / 256, 256>>>();
    k_prep_w<<<(HIDDEN * G4) / 256, 256>>>(W_hh);
    k_prep_wih<<<(KA * G4) / 256, 256>>>(W_ih);
    k_prep_emb<<<((size_t)VOCAB * KA) / 256, 256>>>(emb);

    dim3 gE(G4 / 64, (BATCH * SEQ) / 128);   // (32, 1024)
    k_embed_mma<<<gE, 512, SMEM_EMB>>>(tokens, b_ih);

    k_lstm_persist<<<128, 512, SMEM_PERSIST>>>(b_hh);

    k_fc<<<BATCH, 128>>>(W_fc, b_fc, out);
}